// round 5
// baseline (speedup 1.0000x reference)
#include <cuda_runtime.h>
#include <cuda_bf16.h>
#include <math_constants.h>
#include <cstdint>

// VQ-VAE vector quantizer, GB300 (PTX target sm_103 -> tensor via mma.sync HMMA).
// Round 5: split-bf16 warp MMA distance search + exact fp32 refinement.
// inputs:  d_in[0] = inputs [64,64,32,32] fp32 NCHW, d_in[1] = emb_w [512,64] fp32
// output:  d_out fp32: loss[1] | out[4194304] NCHW | idx[65536]

#define DD        64
#define KK        512
#define NPIX      65536
#define TPB       256
#define WARPS     8
#define TILES     2
#define GRID      128
#define OUT_ELEMS (NPIX * DD)

#define EH_U32    36                    // codebook row stride in u32 (144 B)
#define OFF_EH    0                     // 512*144 = 73728 B
#define OFF_SB    73728                 // 512 fp32 ||e||^2
#define OFF_SCR   75776                 // 16 fp32 scratch
#define OFF_W     75840                 // per-warp buffers
#define W_SZ      9216                  // xh(4608)+xl(4608); reused as 32x65 f32 scores
#define SMEM_TOTAL (OFF_W + WARPS * W_SZ)   // 149568 B

__device__ float g_part[GRID];

__device__ __forceinline__ void mma_bf16(float* c, const uint32_t* a,
                                         uint32_t b0, uint32_t b1) {
    asm volatile(
        "mma.sync.aligned.m16n8k16.row.col.f32.bf16.bf16.f32 "
        "{%0,%1,%2,%3}, {%4,%5,%6,%7}, {%8,%9}, {%0,%1,%2,%3};"
        : "+f"(c[0]), "+f"(c[1]), "+f"(c[2]), "+f"(c[3])
        : "r"(a[0]), "r"(a[1]), "r"(a[2]), "r"(a[3]), "r"(b0), "r"(b1));
}

__global__ __launch_bounds__(TPB, 1)
void vq_main(const float* __restrict__ in, const float* __restrict__ emb,
             float* __restrict__ out) {
    extern __shared__ char smem[];
    uint32_t* ehp = (uint32_t*)(smem + OFF_EH);
    float* sb  = (float*)(smem + OFF_SB);
    float* scr = (float*)(smem + OFF_SCR);
    const int tid = threadIdx.x, wid = tid >> 5, lane = tid & 31;
    const int g = lane >> 2, tq = lane & 3;

    // ---- CTA prologue: bf16-hi codebook (144B rows) + exact ||e_k||^2 ----
    const float2* e2 = (const float2*)emb;
    for (int i = tid; i < KK * 32; i += TPB) {
        int row = i >> 5, c = i & 31;
        float2 v = e2[row * 32 + c];
        ehp[row * EH_U32 + c] =
            (uint32_t)__bfloat16_as_ushort(__float2bfloat16(v.x)) |
            ((uint32_t)__bfloat16_as_ushort(__float2bfloat16(v.y)) << 16);
    }
    for (int k = tid; k < KK; k += TPB) {       // R1-order: rounded squares, seq add
        float s = 0.0f;
        #pragma unroll
        for (int d = 0; d < DD; d++) {
            float v = emb[k * DD + d];
            s = __fadd_rn(s, __fmul_rn(v, v));
        }
        sb[k] = s;
    }
    __syncthreads();

    float mxv = 0.0f;
    for (int k = tid; k < KK; k += TPB) mxv = fmaxf(mxv, sb[k]);
    #pragma unroll
    for (int o = 16; o > 0; o >>= 1) mxv = fmaxf(mxv, __shfl_xor_sync(~0u, mxv, o));
    if (lane == 0) scr[wid] = mxv;
    __syncthreads();
    float m8 = scr[0];
    #pragma unroll
    for (int w = 1; w < WARPS; w++) m8 = fmaxf(m8, scr[w]);
    const float emax = sqrtf(m8);

    uint32_t* xht = (uint32_t*)(smem + OFF_W + wid * W_SZ);
    uint32_t* xlt = xht + 1152;                 // +4608 B
    float*    sbuf = (float*)xht;               // score buffer (reuses tiles)
    float sqacc = 0.0f;

    for (int t = 0; t < TILES; t++) {
        const int n  = blockIdx.x * (TPB * TILES) + t * 256 + wid * 32 + lane;
        const int nb = n >> 10;
        const int hw = n & 1023;
        const float* px = in + (size_t)nb * 65536 + hw;

        // x in regs; A in the R1/R2-proven order; xh/xl bf16 tiles to smem.
        float x[DD];
        #pragma unroll
        for (int d = 0; d < DD; d++) x[d] = px[(size_t)d << 10];
        float a0 = 0.f, a1 = 0.f, a2 = 0.f, a3 = 0.f;
        #pragma unroll
        for (int d = 0; d < DD; d += 4) {
            a0 = __fadd_rn(a0, __fmul_rn(x[d],     x[d]));
            a1 = __fadd_rn(a1, __fmul_rn(x[d + 1], x[d + 1]));
            a2 = __fadd_rn(a2, __fmul_rn(x[d + 2], x[d + 2]));
            a3 = __fadd_rn(a3, __fmul_rn(x[d + 3], x[d + 3]));
        }
        const float A = __fadd_rn(__fadd_rn(a0, a2), __fadd_rn(a1, a3));

        #pragma unroll
        for (int c = 0; c < 32; c++) {
            float v0 = x[2 * c], v1 = x[2 * c + 1];
            __nv_bfloat16 h0 = __float2bfloat16(v0), h1 = __float2bfloat16(v1);
            float r0 = __fsub_rn(v0, __bfloat162float(h0));
            float r1 = __fsub_rn(v1, __bfloat162float(h1));
            xht[lane * EH_U32 + c] =
                (uint32_t)__bfloat16_as_ushort(h0) |
                ((uint32_t)__bfloat16_as_ushort(h1) << 16);
            xlt[lane * EH_U32 + c] =
                (uint32_t)__bfloat16_as_ushort(__float2bfloat16(r0)) |
                ((uint32_t)__bfloat16_as_ushort(__float2bfloat16(r1)) << 16);
        }
        __syncwarp();

        // A fragments (m16n8k16 row-major): reused across all 64 N-tiles.
        uint32_t ah[2][4][4], al[2][4][4];
        #pragma unroll
        for (int m = 0; m < 2; m++)
            #pragma unroll
            for (int ks = 0; ks < 4; ks++) {
                int r0 = (m * 16 + g) * EH_U32, r1 = (m * 16 + g + 8) * EH_U32;
                int c0 = ks * 8 + tq, c1 = c0 + 4;
                ah[m][ks][0] = xht[r0 + c0]; ah[m][ks][1] = xht[r1 + c0];
                ah[m][ks][2] = xht[r0 + c1]; ah[m][ks][3] = xht[r1 + c1];
                al[m][ks][0] = xlt[r0 + c0]; al[m][ks][1] = xlt[r1 + c0];
                al[m][ks][2] = xlt[r0 + c1]; al[m][ks][3] = xlt[r1 + c1];
            }
        __syncwarp();   // frags extracted; tile smem may now be reused for scores

        // Covering margin: 2x the proven 2*2^-9*||x||*emax score-error bound, x2 safety.
        const float margin = fmaf(0.015625f * emax, sqrtf(A), 1.0e-5f);
        float runmin = CUDART_INF_F;
        uint32_t cm[16];

        for (int cc = 0; cc < 8; cc++) {        // 64-code chunks
            #pragma unroll
            for (int nt = 0; nt < 8; nt++) {
                float p0[4] = {0.f, 0.f, 0.f, 0.f};
                float p1[4] = {0.f, 0.f, 0.f, 0.f};
                #pragma unroll
                for (int ks = 0; ks < 4; ks++) {
                    int bi_ = (cc * 64 + nt * 8 + g) * EH_U32 + ks * 8 + tq;
                    uint32_t b0 = ehp[bi_], b1 = ehp[bi_ + 4];
                    mma_bf16(p0, ah[0][ks], b0, b1);
                    mma_bf16(p0, al[0][ks], b0, b1);
                    mma_bf16(p1, ah[1][ks], b0, b1);
                    mma_bf16(p1, al[1][ks], b0, b1);
                }
                // scores s = ||e||^2 - 2*p  (A dropped: shift-invariant)
                int col = nt * 8 + 2 * tq;
                int kb  = cc * 64 + col;
                float s0 = sb[kb], s1 = sb[kb + 1];
                sbuf[(g)      * 65 + col]     = s0 - 2.f * p0[0];
                sbuf[(g)      * 65 + col + 1] = s1 - 2.f * p0[1];
                sbuf[(g + 8)  * 65 + col]     = s0 - 2.f * p0[2];
                sbuf[(g + 8)  * 65 + col + 1] = s1 - 2.f * p0[3];
                sbuf[(g + 16) * 65 + col]     = s0 - 2.f * p1[0];
                sbuf[(g + 16) * 65 + col + 1] = s1 - 2.f * p1[1];
                sbuf[(g + 24) * 65 + col]     = s0 - 2.f * p1[2];
                sbuf[(g + 24) * 65 + col + 1] = s1 - 2.f * p1[3];
            }
            __syncwarp();
            // per-pixel scan of this chunk (lane = pixel row), running-min marks.
            const float* row = sbuf + lane * 65;
            uint32_t m0 = 0, m1 = 0;
            #pragma unroll
            for (int j = 0; j < 32; j++) {
                float dv = row[j];
                if (dv <= runmin + margin) m0 |= (1u << j);
                runmin = fminf(runmin, dv);
            }
            #pragma unroll
            for (int j = 0; j < 32; j++) {
                float dv = row[32 + j];
                if (dv <= runmin + margin) m1 |= (1u << j);
                runmin = fminf(runmin, dv);
            }
            cm[2 * cc] = m0; cm[2 * cc + 1] = m1;
            __syncwarp();
        }

        // Exact refinement (bit-matches R2): ascending k, strict '<'.
        float best = CUDART_INF_F;
        int bi = 0;
        #pragma unroll
        for (int w = 0; w < 16; w++) {
            uint32_t m = cm[w];
            while (m) {
                int j = __ffs(m) - 1;
                m &= m - 1;
                int kk = w * 32 + j;
                const float4* er = (const float4*)(emb + kk * DD);
                float p = 0.0f;
                #pragma unroll
                for (int q = 0; q < DD / 4; q++) {
                    float4 e4 = er[q];
                    p = fmaf(e4.x, x[4 * q + 0], p);
                    p = fmaf(e4.y, x[4 * q + 1], p);
                    p = fmaf(e4.z, x[4 * q + 2], p);
                    p = fmaf(e4.w, x[4 * q + 3], p);
                }
                float dist = __fsub_rn(__fadd_rn(A, sb[kk]), __fmul_rn(2.0f, p));
                if (dist < best) { best = dist; bi = kk; }
            }
        }

        // Epilogue (bit-matches R2): out = fl(x + fl(q - x)), idx, loss partial.
        float* pout = out + 1 + (size_t)nb * 65536 + hw;
        const float* qr = emb + bi * DD;
        #pragma unroll
        for (int d = 0; d < DD; d++) {
            float qd   = qr[d];
            float diff = __fsub_rn(qd, x[d]);
            sqacc = fmaf(diff, diff, sqacc);
            pout[(size_t)d << 10] = __fadd_rn(x[d], diff);
        }
        out[1 + (size_t)OUT_ELEMS + n] = (float)bi;
        __syncwarp();
    }

    // Loss: warp partials -> CTA partial (deterministic, no atomics).
    #pragma unroll
    for (int o = 16; o > 0; o >>= 1)
        sqacc += __shfl_down_sync(~0u, sqacc, o);
    if (lane == 0) scr[wid] = sqacc;
    __syncthreads();
    if (tid == 0) {
        float s = 0.0f;
        #pragma unroll
        for (int w = 0; w < WARPS; w++) s += scr[w];
        g_part[blockIdx.x] = s;
    }
}

__global__ void vq_final(float* __restrict__ out) {
    float s = 0.0f;
    #pragma unroll
    for (int i = 0; i < GRID; i++) s += g_part[i];
    float m = s * (1.0f / (float)OUT_ELEMS);
    out[0] = __fadd_rn(m, __fmul_rn(0.25f, m));
}

extern "C" void kernel_launch(void* const* d_in, const int* in_sizes, int n_in,
                              void* d_out, int out_size) {
    (void)in_sizes; (void)n_in; (void)out_size;
    cudaFuncSetAttribute(vq_main, cudaFuncAttributeMaxDynamicSharedMemorySize,
                         SMEM_TOTAL);
    vq_main<<<GRID, TPB, SMEM_TOTAL>>>((const float*)d_in[0],
                                       (const float*)d_in[1], (float*)d_out);
    vq_final<<<1, 1>>>((float*)d_out);
}

// round 6
// speedup vs baseline: 1.3593x; 1.3593x over previous
#include <cuda_runtime.h>
#include <math_constants.h>
#include <cstdint>

// VQ-VAE vector quantizer, GB300 (PTX sm_103). Round 6: int8 DP4A screening
// (4 MAC/instr) with deterministic covering margin + exact fp32 refinement.
// inputs:  d_in[0] = inputs [64,64,32,32] fp32 NCHW, d_in[1] = emb_w [512,64] fp32
// output:  d_out fp32: loss[1] | out[4194304] NCHW | idx[65536]

#define DD        64
#define KK        512
#define NPIX      65536
#define BLOCK     512
#define GRID      128
#define OUT_ELEMS (NPIX * DD)

#define OFF_E    0                      // int8 codebook [512][64] = 32768 B
#define OFF_B    32768                  // [512] f32 ||e||^2
#define OFF_SCR  34816                  // 64 f32 scratch
#define OFF_MSK  35072                  // [512][17] u32 candidate masks
#define SMEM_TOTAL (OFF_MSK + BLOCK * 17 * 4)   // 69888 B

__device__ float g_part[GRID];

__global__ __launch_bounds__(BLOCK, 1)
void vq_main(const float* __restrict__ in, const float* __restrict__ emb,
             float* __restrict__ out) {
    extern __shared__ char smem[];
    uint4*    Ecb = (uint4*)(smem + OFF_E);     // [512] rows of 4x uint4
    float*    sB  = (float*)(smem + OFF_B);
    float*    scr = (float*)(smem + OFF_SCR);
    uint32_t* msk = (uint32_t*)(smem + OFF_MSK);
    const int tid = threadIdx.x, wid = tid >> 5, lane = tid & 31;

    // ---- codebook prologue: thread t owns code t (BLOCK == KK) ----
    const float* er = emb + tid * DD;
    float Bk = 0.0f, L1e = 0.0f, mxe = 0.0f;
    #pragma unroll 8
    for (int d = 0; d < DD; d++) {
        float v = er[d];
        Bk = __fadd_rn(Bk, __fmul_rn(v, v));    // R1/R2-proven exact order
        float a = fabsf(v);
        L1e += a;
        mxe = fmaxf(mxe, a);
    }
    sB[tid] = Bk;
    float m1 = mxe, m2 = L1e;
    #pragma unroll
    for (int o = 16; o > 0; o >>= 1) {
        m1 = fmaxf(m1, __shfl_xor_sync(~0u, m1, o));
        m2 = fmaxf(m2, __shfl_xor_sync(~0u, m2, o));
    }
    if (lane == 0) { scr[wid] = m1; scr[16 + wid] = m2; }
    __syncthreads();
    float maxe = scr[0], L1emax = scr[16];
    #pragma unroll
    for (int w = 1; w < 16; w++) {
        maxe   = fmaxf(maxe,   scr[w]);
        L1emax = fmaxf(L1emax, scr[16 + w]);
    }
    maxe = fmaxf(maxe, 1e-30f);
    const float se = maxe * (1.0f / 127.0f);
    const float inv_se = 127.0f / maxe;
    {   // quantize + pack own code row: [64] int8 -> 16 u32
        uint32_t* Erow = (uint32_t*)(Ecb + tid * 4);
        #pragma unroll
        for (int i = 0; i < 16; i++) {
            int q0 = __float2int_rn(er[4 * i + 0] * inv_se);
            int q1 = __float2int_rn(er[4 * i + 1] * inv_se);
            int q2 = __float2int_rn(er[4 * i + 2] * inv_se);
            int q3 = __float2int_rn(er[4 * i + 3] * inv_se);
            Erow[i] = (uint32_t)(q0 & 0xFF) | ((uint32_t)(q1 & 0xFF) << 8) |
                      ((uint32_t)(q2 & 0xFF) << 16) | ((uint32_t)(q3 & 0xFF) << 24);
        }
    }
    __syncthreads();

    // ---- pixel: stats pass (A in the proven R1 order, L1, max) ----
    const int n  = blockIdx.x * BLOCK + tid;
    const int b  = n >> 10;
    const int hw = n & 1023;
    const float* px = in + (size_t)b * 65536 + hw;

    float a0 = 0.f, a1 = 0.f, a2 = 0.f, a3 = 0.f, L1x = 0.f, mxx = 0.f;
    #pragma unroll
    for (int d = 0; d < DD; d += 4) {
        float v0 = px[(size_t)(d + 0) << 10];
        float v1 = px[(size_t)(d + 1) << 10];
        float v2 = px[(size_t)(d + 2) << 10];
        float v3 = px[(size_t)(d + 3) << 10];
        a0 = __fadd_rn(a0, __fmul_rn(v0, v0));
        a1 = __fadd_rn(a1, __fmul_rn(v1, v1));
        a2 = __fadd_rn(a2, __fmul_rn(v2, v2));
        a3 = __fadd_rn(a3, __fmul_rn(v3, v3));
        L1x += fabsf(v0) + fabsf(v1) + fabsf(v2) + fabsf(v3);
        mxx = fmaxf(mxx, fmaxf(fmaxf(fabsf(v0), fabsf(v1)),
                               fmaxf(fabsf(v2), fabsf(v3))));
    }
    const float A = __fadd_rn(__fadd_rn(a0, a2), __fadd_rn(a1, a3));
    mxx = fmaxf(mxx, 1e-30f);
    const float sx = mxx * (1.0f / 127.0f);
    const float inv_sx = 127.0f / mxx;

    // pack X (reload x from global: L1-hot)
    uint32_t X[16];
    #pragma unroll
    for (int i = 0; i < 16; i++) {
        int q0 = __float2int_rn(px[(size_t)(4 * i + 0) << 10] * inv_sx);
        int q1 = __float2int_rn(px[(size_t)(4 * i + 1) << 10] * inv_sx);
        int q2 = __float2int_rn(px[(size_t)(4 * i + 2) << 10] * inv_sx);
        int q3 = __float2int_rn(px[(size_t)(4 * i + 3) << 10] * inv_sx);
        X[i] = (uint32_t)(q0 & 0xFF) | ((uint32_t)(q1 & 0xFF) << 8) |
               ((uint32_t)(q2 & 0xFF) << 16) | ((uint32_t)(q3 & 0xFF) << 24);
    }
    const float c2 = -2.0f * sx * se;
    // margin = 2*delta, delta = (sx/2)L1emax + (se/2)L1x + 64*(sx/2)(se/2) + eps
    const float margin = sx * L1emax + se * L1x + 16.0f * sx * se + 1e-6f;

    // ---- DP4A screening with running-min covering marks ----
    float runmin = CUDART_INF_F;
    uint32_t* mrow = msk + tid * 17;
    for (int w = 0; w < 16; w++) {
        uint32_t m = 0;
        const uint4* ep = Ecb + (w * 32) * 4;
        #pragma unroll
        for (int j = 0; j < 32; j++) {
            uint4 q0 = ep[4 * j + 0];
            uint4 q1 = ep[4 * j + 1];
            uint4 q2 = ep[4 * j + 2];
            uint4 q3 = ep[4 * j + 3];
            int P0 = 0, P1 = 0, P2 = 0, P3 = 0;
            P0 = __dp4a((int)X[0],  (int)q0.x, P0);
            P1 = __dp4a((int)X[1],  (int)q0.y, P1);
            P2 = __dp4a((int)X[2],  (int)q0.z, P2);
            P3 = __dp4a((int)X[3],  (int)q0.w, P3);
            P0 = __dp4a((int)X[4],  (int)q1.x, P0);
            P1 = __dp4a((int)X[5],  (int)q1.y, P1);
            P2 = __dp4a((int)X[6],  (int)q1.z, P2);
            P3 = __dp4a((int)X[7],  (int)q1.w, P3);
            P0 = __dp4a((int)X[8],  (int)q2.x, P0);
            P1 = __dp4a((int)X[9],  (int)q2.y, P1);
            P2 = __dp4a((int)X[10], (int)q2.z, P2);
            P3 = __dp4a((int)X[11], (int)q2.w, P3);
            P0 = __dp4a((int)X[12], (int)q3.x, P0);
            P1 = __dp4a((int)X[13], (int)q3.y, P1);
            P2 = __dp4a((int)X[14], (int)q3.z, P2);
            P3 = __dp4a((int)X[15], (int)q3.w, P3);
            int P = (P0 + P1) + (P2 + P3);
            float s = fmaf(c2, (float)P, sB[w * 32 + j]);
            if (s <= runmin + margin) m |= (1u << j);
            runmin = fminf(runmin, s);
        }
        mrow[w] = m;
    }

    // ---- exact refinement (bit-matches R2): ascending k, strict '<' ----
    float x[DD];
    #pragma unroll
    for (int d = 0; d < DD; d++) x[d] = px[(size_t)d << 10];
    float best = CUDART_INF_F;
    int bi = 0;
    for (int w = 0; w < 16; w++) {
        uint32_t m = mrow[w];
        while (m) {
            int j = __ffs(m) - 1;
            m &= m - 1;
            int kk = w * 32 + j;
            const float4* e4p = (const float4*)(emb + kk * DD);
            float p = 0.0f;
            #pragma unroll
            for (int q = 0; q < DD / 4; q++) {
                float4 e4 = e4p[q];
                p = fmaf(e4.x, x[4 * q + 0], p);
                p = fmaf(e4.y, x[4 * q + 1], p);
                p = fmaf(e4.z, x[4 * q + 2], p);
                p = fmaf(e4.w, x[4 * q + 3], p);
            }
            float dist = __fsub_rn(__fadd_rn(A, sB[kk]), __fmul_rn(2.0f, p));
            if (dist < best) { best = dist; bi = kk; }
        }
    }

    // ---- epilogue (bit-matches R2) ----
    float* pout = out + 1 + (size_t)b * 65536 + hw;
    const float* qr = emb + bi * DD;
    float sq = 0.0f;
    #pragma unroll
    for (int d = 0; d < DD; d++) {
        float qd   = qr[d];
        float diff = __fsub_rn(qd, x[d]);
        sq = fmaf(diff, diff, sq);
        pout[(size_t)d << 10] = __fadd_rn(x[d], diff);
    }
    out[1 + (size_t)OUT_ELEMS + n] = (float)bi;

    // ---- loss partial: deterministic block reduction ----
    __syncthreads();   // scr reads above are long done; safe to reuse
    #pragma unroll
    for (int o = 16; o > 0; o >>= 1)
        sq += __shfl_down_sync(~0u, sq, o);
    if (lane == 0) scr[wid] = sq;
    __syncthreads();
    if (tid == 0) {
        float s = 0.0f;
        #pragma unroll
        for (int w = 0; w < 16; w++) s += scr[w];
        g_part[blockIdx.x] = s;
    }
}

__global__ void vq_final(float* __restrict__ out) {
    float s = 0.0f;
    #pragma unroll
    for (int i = 0; i < GRID; i++) s += g_part[i];
    float m = s * (1.0f / (float)OUT_ELEMS);
    out[0] = __fadd_rn(m, __fmul_rn(0.25f, m));
}

extern "C" void kernel_launch(void* const* d_in, const int* in_sizes, int n_in,
                              void* d_out, int out_size) {
    (void)in_sizes; (void)n_in; (void)out_size;
    cudaFuncSetAttribute(vq_main, cudaFuncAttributeMaxDynamicSharedMemorySize,
                         SMEM_TOTAL);
    vq_main<<<GRID, BLOCK, SMEM_TOTAL>>>((const float*)d_in[0],
                                         (const float*)d_in[1], (float*)d_out);
    vq_final<<<1, 1>>>((float*)d_out);
}

// round 7
// speedup vs baseline: 1.3783x; 1.0140x over previous
#include <cuda_runtime.h>
#include <math_constants.h>
#include <cstdint>

// VQ-VAE vector quantizer, GB300 (PTX sm_103). Round 7: DP4A screening with
// low-pressure loop (unroll 4, single chain, shift-insert masks) + exact fp32
// refinement; single kernel (last-CTA loss finalize) for profiler visibility.
// inputs:  d_in[0] = inputs [64,64,32,32] fp32 NCHW, d_in[1] = emb_w [512,64] fp32
// output:  d_out fp32: loss[1] | out[4194304] NCHW | idx[65536]

#define DD        64
#define KK        512
#define NPIX      65536
#define BLOCK     512
#define GRID      128
#define OUT_ELEMS (NPIX * DD)

#define OFF_E    0                      // int8 codebook [512][64] = 32768 B
#define OFF_B    32768                  // [512] f32 ||e||^2
#define OFF_SCR  34816                  // 64 f32 scratch
#define OFF_MSK  35072                  // [512][17] u32 candidate masks
#define SMEM_TOTAL (OFF_MSK + BLOCK * 17 * 4)   // 69888 B

__device__ float g_part[GRID];
__device__ unsigned int g_cnt;          // zero-initialized; left at 0 every run

__global__ __launch_bounds__(BLOCK, 1)
void vq_main(const float* __restrict__ in, const float* __restrict__ emb,
             float* __restrict__ out) {
    extern __shared__ char smem[];
    uint4*    Ecb = (uint4*)(smem + OFF_E);
    float*    sB  = (float*)(smem + OFF_B);
    float*    scr = (float*)(smem + OFF_SCR);
    uint32_t* msk = (uint32_t*)(smem + OFF_MSK);
    const int tid = threadIdx.x, wid = tid >> 5, lane = tid & 31;

    // ---- codebook prologue: thread t owns code t (BLOCK == KK) ----
    const float* er = emb + tid * DD;
    float Bk = 0.0f, L1e = 0.0f, mxe = 0.0f;
    #pragma unroll 8
    for (int d = 0; d < DD; d++) {
        float v = er[d];
        Bk = __fadd_rn(Bk, __fmul_rn(v, v));    // R1/R2-proven exact order
        float a = fabsf(v);
        L1e += a;
        mxe = fmaxf(mxe, a);
    }
    sB[tid] = Bk;
    float m1 = mxe, m2 = L1e;
    #pragma unroll
    for (int o = 16; o > 0; o >>= 1) {
        m1 = fmaxf(m1, __shfl_xor_sync(~0u, m1, o));
        m2 = fmaxf(m2, __shfl_xor_sync(~0u, m2, o));
    }
    if (lane == 0) { scr[wid] = m1; scr[16 + wid] = m2; }
    __syncthreads();
    float maxe = scr[0], L1emax = scr[16];
    #pragma unroll
    for (int w = 1; w < 16; w++) {
        maxe   = fmaxf(maxe,   scr[w]);
        L1emax = fmaxf(L1emax, scr[16 + w]);
    }
    maxe = fmaxf(maxe, 1e-30f);
    const float se = maxe * (1.0f / 127.0f);
    const float inv_se = 127.0f / maxe;
    {   // quantize + pack own code row: [64] int8 -> 16 u32
        uint32_t* Erow = (uint32_t*)(Ecb + tid * 4);
        #pragma unroll
        for (int i = 0; i < 16; i++) {
            int q0 = __float2int_rn(er[4 * i + 0] * inv_se);
            int q1 = __float2int_rn(er[4 * i + 1] * inv_se);
            int q2 = __float2int_rn(er[4 * i + 2] * inv_se);
            int q3 = __float2int_rn(er[4 * i + 3] * inv_se);
            Erow[i] = (uint32_t)(q0 & 0xFF) | ((uint32_t)(q1 & 0xFF) << 8) |
                      ((uint32_t)(q2 & 0xFF) << 16) | ((uint32_t)(q3 & 0xFF) << 24);
        }
    }
    __syncthreads();

    // ---- pixel stats (A in the proven R1 order, L1, max) ----
    const int n  = blockIdx.x * BLOCK + tid;
    const int b  = n >> 10;
    const int hw = n & 1023;
    const float* px = in + (size_t)b * 65536 + hw;

    float a0 = 0.f, a1 = 0.f, a2 = 0.f, a3 = 0.f, L1x = 0.f, mxx = 0.f;
    #pragma unroll
    for (int d = 0; d < DD; d += 4) {
        float v0 = px[(size_t)(d + 0) << 10];
        float v1 = px[(size_t)(d + 1) << 10];
        float v2 = px[(size_t)(d + 2) << 10];
        float v3 = px[(size_t)(d + 3) << 10];
        a0 = __fadd_rn(a0, __fmul_rn(v0, v0));
        a1 = __fadd_rn(a1, __fmul_rn(v1, v1));
        a2 = __fadd_rn(a2, __fmul_rn(v2, v2));
        a3 = __fadd_rn(a3, __fmul_rn(v3, v3));
        L1x += fabsf(v0) + fabsf(v1) + fabsf(v2) + fabsf(v3);
        mxx = fmaxf(mxx, fmaxf(fmaxf(fabsf(v0), fabsf(v1)),
                               fmaxf(fabsf(v2), fabsf(v3))));
    }
    const float A = __fadd_rn(__fadd_rn(a0, a2), __fadd_rn(a1, a3));
    mxx = fmaxf(mxx, 1e-30f);
    const float sx = mxx * (1.0f / 127.0f);
    const float inv_sx = 127.0f / mxx;

    uint32_t X[16];
    #pragma unroll
    for (int i = 0; i < 16; i++) {
        int q0 = __float2int_rn(px[(size_t)(4 * i + 0) << 10] * inv_sx);
        int q1 = __float2int_rn(px[(size_t)(4 * i + 1) << 10] * inv_sx);
        int q2 = __float2int_rn(px[(size_t)(4 * i + 2) << 10] * inv_sx);
        int q3 = __float2int_rn(px[(size_t)(4 * i + 3) << 10] * inv_sx);
        X[i] = (uint32_t)(q0 & 0xFF) | ((uint32_t)(q1 & 0xFF) << 8) |
               ((uint32_t)(q2 & 0xFF) << 16) | ((uint32_t)(q3 & 0xFF) << 24);
    }
    const float c2 = -2.0f * sx * se;
    // covering margin = 2*delta (quantization error bound), + eps
    const float margin = sx * L1emax + se * L1x + 16.0f * sx * se + 1e-6f;

    // ---- DP4A screening; marks provably cover the true argmin ----
    // thr = prefix-min of fl(s+margin) == fl(prefmin(s)+margin) (monotone fl).
    float thr = CUDART_INF_F;
    uint32_t* mrow = msk + tid * 17;
    #pragma unroll 1
    for (int w = 0; w < 16; w++) {
        uint32_t m = 0;
        const uint4* ep = Ecb + (w * 32) * 4;
        const float* bp = sB + w * 32;
        #pragma unroll 4
        for (int j = 0; j < 32; j++) {
            uint4 q0 = ep[4 * j + 0];
            uint4 q1 = ep[4 * j + 1];
            uint4 q2 = ep[4 * j + 2];
            uint4 q3 = ep[4 * j + 3];
            int P = 0;
            P = __dp4a((int)X[0],  (int)q0.x, P);
            P = __dp4a((int)X[1],  (int)q0.y, P);
            P = __dp4a((int)X[2],  (int)q0.z, P);
            P = __dp4a((int)X[3],  (int)q0.w, P);
            P = __dp4a((int)X[4],  (int)q1.x, P);
            P = __dp4a((int)X[5],  (int)q1.y, P);
            P = __dp4a((int)X[6],  (int)q1.z, P);
            P = __dp4a((int)X[7],  (int)q1.w, P);
            P = __dp4a((int)X[8],  (int)q2.x, P);
            P = __dp4a((int)X[9],  (int)q2.y, P);
            P = __dp4a((int)X[10], (int)q2.z, P);
            P = __dp4a((int)X[11], (int)q2.w, P);
            P = __dp4a((int)X[12], (int)q3.x, P);
            P = __dp4a((int)X[13], (int)q3.y, P);
            P = __dp4a((int)X[14], (int)q3.z, P);
            P = __dp4a((int)X[15], (int)q3.w, P);
            float s = fmaf(c2, (float)P, bp[j]);
            m = (m >> 1) | ((s <= thr) ? 0x80000000u : 0u);  // bit j after 32 steps
            thr = fminf(thr, __fadd_rn(s, margin));
        }
        mrow[w] = m;
    }

    // ---- exact refinement (bit-matches R2): ascending k, strict '<' ----
    float x[DD];
    #pragma unroll
    for (int d = 0; d < DD; d++) x[d] = px[(size_t)d << 10];
    float best = CUDART_INF_F;
    int bi = 0;
    for (int w = 0; w < 16; w++) {
        uint32_t m = mrow[w];
        while (m) {
            int j = __ffs(m) - 1;
            m &= m - 1;
            int kk = w * 32 + j;
            const float4* e4p = (const float4*)(emb + kk * DD);
            float p = 0.0f;
            #pragma unroll
            for (int q = 0; q < DD / 4; q++) {
                float4 e4 = e4p[q];
                p = fmaf(e4.x, x[4 * q + 0], p);
                p = fmaf(e4.y, x[4 * q + 1], p);
                p = fmaf(e4.z, x[4 * q + 2], p);
                p = fmaf(e4.w, x[4 * q + 3], p);
            }
            float dist = __fsub_rn(__fadd_rn(A, sB[kk]), __fmul_rn(2.0f, p));
            if (dist < best) { best = dist; bi = kk; }
        }
    }

    // ---- epilogue (bit-matches R2) ----
    float* pout = out + 1 + (size_t)b * 65536 + hw;
    const float* qr = emb + bi * DD;
    float sq = 0.0f;
    #pragma unroll
    for (int d = 0; d < DD; d++) {
        float qd   = qr[d];
        float diff = __fsub_rn(qd, x[d]);
        sq = fmaf(diff, diff, sq);
        pout[(size_t)d << 10] = __fadd_rn(x[d], diff);
    }
    out[1 + (size_t)OUT_ELEMS + n] = (float)bi;

    // ---- loss: block reduce -> per-CTA partial; last CTA finalizes ----
    __syncthreads();
    #pragma unroll
    for (int o = 16; o > 0; o >>= 1)
        sq += __shfl_down_sync(~0u, sq, o);
    if (lane == 0) scr[wid] = sq;
    __syncthreads();
    if (tid == 0) {
        float s = 0.0f;
        #pragma unroll
        for (int w = 0; w < 16; w++) s += scr[w];
        g_part[blockIdx.x] = s;
        __threadfence();
        unsigned int prev = atomicAdd(&g_cnt, 1u);
        if (prev == GRID - 1) {                 // last CTA: deterministic sum
            float tot = 0.0f;
            volatile float* gp = g_part;
            #pragma unroll
            for (int i = 0; i < GRID; i++) tot += gp[i];
            float mmean = tot * (1.0f / (float)OUT_ELEMS);
            out[0] = __fadd_rn(mmean, __fmul_rn(0.25f, mmean));
            g_cnt = 0u;                         // reset for next replay
        }
    }
}

extern "C" void kernel_launch(void* const* d_in, const int* in_sizes, int n_in,
                              void* d_out, int out_size) {
    (void)in_sizes; (void)n_in; (void)out_size;
    cudaFuncSetAttribute(vq_main, cudaFuncAttributeMaxDynamicSharedMemorySize,
                         SMEM_TOTAL);
    vq_main<<<GRID, BLOCK, SMEM_TOTAL>>>((const float*)d_in[0],
                                         (const float*)d_in[1], (float*)d_out);
}